// round 3
// baseline (speedup 1.0000x reference)
#include <cuda_runtime.h>
#include <math.h>

#define HW   262144
#define DD   256
#define VV   32
#define NF   256
#define NPART 256

// ---------------- scratch (device globals) --------------------------------
__device__ float g_iv2[DD*VV];
__device__ float g_nw2[DD*VV];      // -2 * W * iv2
__device__ float g_c[VV];           // sum_d W^2 * iv2
__device__ float g_Q[HW*VV];        // 32 MB
__device__ float g_Mpart[NPART*DD*VV];
__device__ float g_spart[NPART*VV];
__device__ float g_M[DD*VV];
__device__ float g_s[VV];
__device__ float g_Z[DD*VV];
__device__ float g_Adj[VV*VV];
__device__ float g_T1[VV*NF];
__device__ float g_Zo[VV*NF];

// ---------------- packed f32x2 helpers -----------------------------------
typedef unsigned long long ull;
__device__ __forceinline__ ull pk2(float lo, float hi){
    ull r; asm("mov.b64 %0,{%1,%2};" : "=l"(r) : "f"(lo), "f"(hi)); return r;
}
__device__ __forceinline__ float2 up2(ull v){
    float2 r; asm("mov.b64 {%0,%1},%2;" : "=f"(r.x), "=f"(r.y) : "l"(v)); return r;
}
__device__ __forceinline__ ull f2fma(ull a, ull b, ull c){
    ull d; asm("fma.rn.f32x2 %0,%1,%2,%3;" : "=l"(d) : "l"(a), "l"(b), "l"(c)); return d;
}

// ---------------- kernel 0: precompute tables ----------------------------
__global__ void k_prep(const float* __restrict__ W, const float* __restrict__ var){
    int e = blockIdx.x*256 + threadIdx.x;
    float iv  = 1.0f / var[e];
    float iv2 = iv*iv;
    g_iv2[e] = iv2;
    g_nw2[e] = -2.0f * W[e] * iv2;
}
__global__ void k_prep_c(const float* __restrict__ W){
    int v = threadIdx.x;
    float c = 0.0f;
    for(int d=0; d<DD; d++){
        float w = W[d*VV+v];
        c = fmaf(w*w, g_iv2[d*VV+v], c);
    }
    g_c[v] = c;
}

// ---------------- kernel 1a: Q pass (fused 2 GEMMs + softmax) -------------
// block 256; quad: vg=tid&3 owns v=vg*8..+8, pg=tid>>2 owns points pg*8..+8.
// 512 points/block, grid 512.
__global__ __launch_bounds__(256, 2) void k_qpass(const float* __restrict__ X){
    extern __shared__ float sm[];
    float* xs  = sm;                 // 512*33
    float* ivc = sm + 512*33;        // 32*32
    float* nwc = ivc + 1024;         // 32*32
    float* c_s = nwc + 1024;         // 32

    const int tid = threadIdx.x;
    const int vg = tid & 3, pg = tid >> 2;
    const int pbase = blockIdx.x * 512;
    if(tid < VV) c_s[tid] = g_c[tid];

    ull acc[8][4];
    #pragma unroll
    for(int pp=0;pp<8;pp++){ acc[pp][0]=0; acc[pp][1]=0; acc[pp][2]=0; acc[pp][3]=0; }

    for(int ch=0; ch<8; ch++){
        __syncthreads();
        {   // stage table chunk (1024 floats each)
            float4 a = ((const float4*)(g_iv2 + ch*1024))[tid];
            ((float4*)ivc)[tid] = a;
            float4 b = ((const float4*)(g_nw2 + ch*1024))[tid];
            ((float4*)nwc)[tid] = b;
        }
        // stage X: 512 pts x 32 d
        #pragma unroll
        for(int i=tid; i<512*8; i+=256){
            int pl = i >> 3, dq = (i & 7) * 4;
            float4 v = *(const float4*)(X + (size_t)(pbase+pl)*DD + ch*32 + dq);
            float* dst = xs + pl*33 + dq;
            dst[0]=v.x; dst[1]=v.y; dst[2]=v.z; dst[3]=v.w;
        }
        __syncthreads();

        const float* xrow = xs + pg*8*33;
        #pragma unroll 2
        for(int d=0; d<32; d++){
            const ulonglong2* ap = (const ulonglong2*)(ivc + d*32 + vg*8);
            const ulonglong2* bp = (const ulonglong2*)(nwc + d*32 + vg*8);
            ulonglong2 a0 = ap[0], a1 = ap[1];
            ulonglong2 b0 = bp[0], b1 = bp[1];
            float xv[8];
            #pragma unroll
            for(int pp=0;pp<8;pp++) xv[pp] = xrow[pp*33 + d];
            #pragma unroll
            for(int pp=0;pp<8;pp++){
                ull xp = pk2(xv[pp], xv[pp]);
                ull t;
                t = f2fma(xp, a0.x, b0.x); acc[pp][0] = f2fma(xp, t, acc[pp][0]);
                t = f2fma(xp, a0.y, b0.y); acc[pp][1] = f2fma(xp, t, acc[pp][1]);
                t = f2fma(xp, a1.x, b1.x); acc[pp][2] = f2fma(xp, t, acc[pp][2]);
                t = f2fma(xp, a1.y, b1.y); acc[pp][3] = f2fma(xp, t, acc[pp][3]);
            }
        }
    }

    // epilogue: quad-wide softmax
    #pragma unroll
    for(int pp=0;pp<8;pp++){
        int p = pbase + pg*8 + pp;
        float qa[8];
        #pragma unroll
        for(int q=0;q<4;q++){
            float2 f = up2(acc[pp][q]);
            qa[2*q]   = f.x + c_s[vg*8 + 2*q];
            qa[2*q+1] = f.y + c_s[vg*8 + 2*q+1];
        }
        float mn = qa[0];
        #pragma unroll
        for(int i=1;i<8;i++) mn = fminf(mn, qa[i]);
        mn = fminf(mn, __shfl_xor_sync(0xffffffffu, mn, 1));
        mn = fminf(mn, __shfl_xor_sync(0xffffffffu, mn, 2));
        float sum = 0.0f;
        #pragma unroll
        for(int i=0;i<8;i++){ float e = __expf(-0.5f*(qa[i]-mn)); qa[i]=e; sum+=e; }
        sum += __shfl_xor_sync(0xffffffffu, sum, 1);
        sum += __shfl_xor_sync(0xffffffffu, sum, 2);
        float inv = 1.0f / sum;
        float4* dst = (float4*)(g_Q + (size_t)p*VV + vg*8);
        dst[0] = make_float4(qa[0]*inv, qa[1]*inv, qa[2]*inv, qa[3]*inv);
        dst[1] = make_float4(qa[4]*inv, qa[5]*inv, qa[6]*inv, qa[7]*inv);
    }
}

// ---------------- kernel 1b: M = X^T Q partials, s = colsum(Q) ------------
// block 128; thread owns d = tid and tid+128. 1024 points/block, grid 256.
__global__ __launch_bounds__(128) void k_mpass(const float* __restrict__ X){
    __shared__ __align__(16) float qs[32*VV];    // 32-point Q tile
    __shared__ float ssh[128*8];
    const int tid = threadIdx.x;
    const int pbase = blockIdx.x * 1024;

    ull m0[16], m1[16];                          // m[2j],m[2j+1] <-> v=4j..4j+3
    #pragma unroll
    for(int i=0;i<16;i++){ m0[i]=0; m1[i]=0; }
    float svec[8];
    #pragma unroll
    for(int i=0;i<8;i++) svec[i]=0.0f;

    for(int it=0; it<32; it++){
        __syncthreads();
        {   // stage 32 points x 32 v, accumulate colsum partials
            const float4* src = (const float4*)(g_Q + (size_t)(pbase + it*32)*VV);
            float4 a = src[tid*2], b = src[tid*2+1];
            ((float4*)qs)[tid*2]   = a;
            ((float4*)qs)[tid*2+1] = b;
            svec[0]+=a.x; svec[1]+=a.y; svec[2]+=a.z; svec[3]+=a.w;
            svec[4]+=b.x; svec[5]+=b.y; svec[6]+=b.z; svec[7]+=b.w;
        }
        __syncthreads();

        const float* xp = X + (size_t)(pbase + it*32)*DD + tid;
        #pragma unroll
        for(int pb=0; pb<32; pb+=8){
            float x0[8], x1[8];
            #pragma unroll
            for(int k=0;k<8;k++){
                x0[k] = xp[(pb+k)*DD];
                x1[k] = xp[(pb+k)*DD + 128];
            }
            #pragma unroll
            for(int k=0;k<8;k++){
                ull xa = pk2(x0[k], x0[k]);
                ull xb = pk2(x1[k], x1[k]);
                const ulonglong2* qrow = (const ulonglong2*)(qs + (pb+k)*VV);
                #pragma unroll
                for(int j=0;j<8;j++){           // FIXED: 8 ulonglong2 = 32 v
                    ulonglong2 qq = qrow[j];
                    m0[2*j  ] = f2fma(xa, qq.x, m0[2*j  ]);
                    m0[2*j+1] = f2fma(xa, qq.y, m0[2*j+1]);
                    m1[2*j  ] = f2fma(xb, qq.x, m1[2*j  ]);
                    m1[2*j+1] = f2fma(xb, qq.y, m1[2*j+1]);
                }
            }
        }
    }
    float* mp0 = g_Mpart + (size_t)blockIdx.x*DD*VV + tid*VV;
    float* mp1 = mp0 + 128*VV;
    #pragma unroll
    for(int j=0;j<16;j++){
        float2 f;
        f = up2(m0[j]); mp0[2*j]=f.x; mp0[2*j+1]=f.y;
        f = up2(m1[j]); mp1[2*j]=f.x; mp1[2*j+1]=f.y;
    }
    // colsum partials: thread covered v = (tid%4)*8 .. +8
    #pragma unroll
    for(int i=0;i<8;i++) ssh[tid*8+i] = svec[i];
    __syncthreads();
    if(tid < VV){
        int v = tid;
        float s = 0.0f;
        #pragma unroll
        for(int g=0; g<32; g++) s += ssh[((v>>3) + 4*g)*8 + (v&7)];
        g_spart[blockIdx.x*VV + v] = s;
    }
}

// ---------------- kernel 2a: deterministic reduction ----------------------
__global__ void k_reduce(){
    if(blockIdx.x < 32){
        int e = blockIdx.x*256 + threadIdx.x;
        float s = 0.0f;
        for(int part=0; part<NPART; part++) s += g_Mpart[(size_t)part*DD*VV + e];
        g_M[e] = s;
    } else if(threadIdx.x < VV){
        float s = 0.0f;
        for(int part=0; part<NPART; part++) s += g_spart[part*VV + threadIdx.x];
        g_s[threadIdx.x] = s;
    }
}

// ---------------- kernel 2b: Z, normalize, Adj = Z^T Z --------------------
__global__ __launch_bounds__(256) void k_z(const float* __restrict__ W,
                                           const float* __restrict__ var){
    __shared__ float Zs[DD*33];
    __shared__ float s_s[VV], cs[VV];
    const int tid = threadIdx.x;
    if(tid < VV) s_s[tid] = g_s[tid];
    __syncthreads();

    #pragma unroll
    for(int v=0; v<VV; v++){
        int e = tid*VV + v;
        float sv = s_s[v];
        float z = (g_M[e] - W[e]*sv) * (1.0f/var[e]) / sv;
        Zs[tid*33 + v] = z;
    }
    __syncthreads();
    if(tid < VV){
        float acc = 0.0f;
        for(int d=0; d<DD; d++){ float z = Zs[d*33+tid]; acc = fmaf(z,z,acc); }
        cs[tid] = acc;
    }
    __syncthreads();
    #pragma unroll
    for(int v=0; v<VV; v++){
        float z = Zs[tid*33 + v] / cs[v];
        Zs[tid*33 + v] = z;
        g_Z[tid*VV + v] = z;
    }
    __syncthreads();
    for(int k=0;k<4;k++){
        int e = k*256 + tid;
        int i = e >> 5, j = e & 31;
        float acc = 0.0f;
        for(int d=0; d<DD; d++) acc = fmaf(Zs[d*33+i], Zs[d*33+j], acc);
        g_Adj[e] = acc;
    }
}

// ---------------- kernel 2c/2d: T1, Zo ------------------------------------
__global__ void k_t1(const float* __restrict__ weight){
    int v = blockIdx.x, f = threadIdx.x;
    float acc = 0.0f;
    for(int d=0; d<DD; d++) acc = fmaf(g_Z[d*VV+v], weight[d*NF+f], acc);
    g_T1[v*NF + f] = acc;
}
__global__ void k_zo(){
    int v = blockIdx.x, f = threadIdx.x;
    float acc = 0.0f;
    #pragma unroll
    for(int j=0;j<VV;j++) acc = fmaf(g_Adj[v*VV+j], g_T1[j*NF+f], acc);
    g_Zo[v*NF + f] = fmaxf(acc, 0.0f);
}

// ---------------- kernel 3: Xn = Q @ Zo -> out ----------------------------
__global__ __launch_bounds__(256) void k_out(float* __restrict__ out){
    __shared__ __align__(16) float zo[VV*NF];
    __shared__ __align__(16) float qts[8][264];

    const int tid = threadIdx.x, w = tid >> 5, l = tid & 31;
    for(int i=tid; i<VV*NF; i+=256) zo[i] = g_Zo[i];
    __syncthreads();

    const int pbase = blockIdx.x*64 + w*8;
    {
        const float4* src = (const float4*)(g_Q + (size_t)(pbase + (l>>2))*VV + (l&3)*8);
        float4 a = src[0], b = src[1];
        int p = l >> 2, vb = (l & 3)*8;
        float* dst = qts[w];
        dst[(vb+0)*8+p]=a.x; dst[(vb+1)*8+p]=a.y; dst[(vb+2)*8+p]=a.z; dst[(vb+3)*8+p]=a.w;
        dst[(vb+4)*8+p]=b.x; dst[(vb+5)*8+p]=b.y; dst[(vb+6)*8+p]=b.z; dst[(vb+7)*8+p]=b.w;
    }
    __syncwarp();

    ull acc[8][4];
    #pragma unroll
    for(int p=0;p<8;p++){ acc[p][0]=0; acc[p][1]=0; acc[p][2]=0; acc[p][3]=0; }

    #pragma unroll 4
    for(int v=0; v<VV; v++){
        ulonglong2 zA = *(const ulonglong2*)(zo + v*NF + l*4);
        ulonglong2 zB = *(const ulonglong2*)(zo + v*NF + 128 + l*4);
        const float* qv = qts[w] + v*8;
        float4 qA = *(const float4*)(qv);
        float4 qB = *(const float4*)(qv+4);
        float qf[8] = {qA.x,qA.y,qA.z,qA.w,qB.x,qB.y,qB.z,qB.w};
        #pragma unroll
        for(int p=0;p<8;p++){
            ull qp = pk2(qf[p], qf[p]);
            acc[p][0] = f2fma(qp, zA.x, acc[p][0]);
            acc[p][1] = f2fma(qp, zA.y, acc[p][1]);
            acc[p][2] = f2fma(qp, zB.x, acc[p][2]);
            acc[p][3] = f2fma(qp, zB.y, acc[p][3]);
        }
    }
    #pragma unroll
    for(int p=0;p<8;p++){
        float2 f0=up2(acc[p][0]), f1=up2(acc[p][1]);
        float2 f2v=up2(acc[p][2]), f3=up2(acc[p][3]);
        float* base = out + (size_t)(pbase+p)*NF;
        *(float4*)(base + l*4)       = make_float4(f0.x,f0.y,f1.x,f1.y);
        *(float4*)(base + 128 + l*4) = make_float4(f2v.x,f2v.y,f3.x,f3.y);
    }
}

// ---------------- launch ---------------------------------------------------
extern "C" void kernel_launch(void* const* d_in, const int* in_sizes, int n_in,
                              void* d_out, int out_size){
    const float* X      = (const float*)d_in[0];
    const float* W      = (const float*)d_in[1];
    const float* var    = (const float*)d_in[2];
    const float* weight = (const float*)d_in[3];
    float* out = (float*)d_out;

    static int smem_set = 0;
    const int qp_smem = (512*33 + 2048 + 32) * 4;
    if(!smem_set){
        cudaFuncSetAttribute(k_qpass, cudaFuncAttributeMaxDynamicSharedMemorySize, qp_smem);
        smem_set = 1;
    }

    k_prep  <<<32, 256>>>(W, var);
    k_prep_c<<<1, 32>>>(W);
    k_qpass <<<HW/512, 256, qp_smem>>>(X);
    k_mpass <<<NPART, 128>>>(X);
    k_reduce<<<33, 256>>>();
    k_z     <<<1, 256>>>(W, var);
    k_t1    <<<VV, 256>>>(weight);
    k_zo    <<<VV, 256>>>();
    k_out   <<<HW/64, 256>>>(out);
}

// round 7
// speedup vs baseline: 1.1291x; 1.1291x over previous
#include <cuda_runtime.h>
#include <math.h>

#define HW   262144
#define DD   256
#define VV   32
#define NF   256
#define NPART 512

// ---------------- scratch (device globals) --------------------------------
__device__ float g_iv2[DD*VV];
__device__ float g_nw2[DD*VV];      // -2 * W * iv2
__device__ float g_c[VV];           // sum_d W^2 * iv2
__device__ float g_Q[HW*VV];        // 32 MB
__device__ float g_Mpart[NPART*DD*VV];
__device__ float g_spart[NPART*VV];
__device__ float g_M[DD*VV];
__device__ float g_s[VV];
__device__ float g_Z[DD*VV];
__device__ float g_Adj[VV*VV];
__device__ float g_T1[VV*NF];
__device__ float g_Zo[VV*NF];

// ---------------- packed f32x2 helpers -----------------------------------
typedef unsigned long long ull;
__device__ __forceinline__ ull pk2(float lo, float hi){
    ull r; asm("mov.b64 %0,{%1,%2};" : "=l"(r) : "f"(lo), "f"(hi)); return r;
}
__device__ __forceinline__ float2 up2(ull v){
    float2 r; asm("mov.b64 {%0,%1},%2;" : "=f"(r.x), "=f"(r.y) : "l"(v)); return r;
}
__device__ __forceinline__ ull f2fma(ull a, ull b, ull c){
    ull d; asm("fma.rn.f32x2 %0,%1,%2,%3;" : "=l"(d) : "l"(a), "l"(b), "l"(c)); return d;
}

// ---------------- kernel 0: precompute tables ----------------------------
__global__ void k_prep(const float* __restrict__ W, const float* __restrict__ var){
    int e = blockIdx.x*256 + threadIdx.x;
    float iv  = 1.0f / var[e];
    float iv2 = iv*iv;
    g_iv2[e] = iv2;
    g_nw2[e] = -2.0f * W[e] * iv2;
}
__global__ void k_prep_c(const float* __restrict__ W){
    int v = threadIdx.x;
    float c = 0.0f;
    for(int d=0; d<DD; d++){
        float w = W[d*VV+v];
        c = fmaf(w*w, g_iv2[d*VV+v], c);
    }
    g_c[v] = c;
}

// ---------------- kernel 1a: Q pass (fused 2 GEMMs + softmax) -------------
// block 256; quad: vg=tid&3 owns v=vg*8..+8, pg=tid>>2 owns points pg*8..+8.
// 512 points/block, grid 512.   (unchanged from round 3 — passing)
__global__ __launch_bounds__(256, 2) void k_qpass(const float* __restrict__ X){
    extern __shared__ float sm[];
    float* xs  = sm;                 // 512*33
    float* ivc = sm + 512*33;        // 32*32
    float* nwc = ivc + 1024;         // 32*32
    float* c_s = nwc + 1024;         // 32

    const int tid = threadIdx.x;
    const int vg = tid & 3, pg = tid >> 2;
    const int pbase = blockIdx.x * 512;
    if(tid < VV) c_s[tid] = g_c[tid];

    ull acc[8][4];
    #pragma unroll
    for(int pp=0;pp<8;pp++){ acc[pp][0]=0; acc[pp][1]=0; acc[pp][2]=0; acc[pp][3]=0; }

    for(int ch=0; ch<8; ch++){
        __syncthreads();
        {   // stage table chunk (1024 floats each)
            float4 a = ((const float4*)(g_iv2 + ch*1024))[tid];
            ((float4*)ivc)[tid] = a;
            float4 b = ((const float4*)(g_nw2 + ch*1024))[tid];
            ((float4*)nwc)[tid] = b;
        }
        // stage X: 512 pts x 32 d
        #pragma unroll
        for(int i=tid; i<512*8; i+=256){
            int pl = i >> 3, dq = (i & 7) * 4;
            float4 v = *(const float4*)(X + (size_t)(pbase+pl)*DD + ch*32 + dq);
            float* dst = xs + pl*33 + dq;
            dst[0]=v.x; dst[1]=v.y; dst[2]=v.z; dst[3]=v.w;
        }
        __syncthreads();

        const float* xrow = xs + pg*8*33;
        #pragma unroll 2
        for(int d=0; d<32; d++){
            const ulonglong2* ap = (const ulonglong2*)(ivc + d*32 + vg*8);
            const ulonglong2* bp = (const ulonglong2*)(nwc + d*32 + vg*8);
            ulonglong2 a0 = ap[0], a1 = ap[1];
            ulonglong2 b0 = bp[0], b1 = bp[1];
            float xv[8];
            #pragma unroll
            for(int pp=0;pp<8;pp++) xv[pp] = xrow[pp*33 + d];
            #pragma unroll
            for(int pp=0;pp<8;pp++){
                ull xp = pk2(xv[pp], xv[pp]);
                ull t;
                t = f2fma(xp, a0.x, b0.x); acc[pp][0] = f2fma(xp, t, acc[pp][0]);
                t = f2fma(xp, a0.y, b0.y); acc[pp][1] = f2fma(xp, t, acc[pp][1]);
                t = f2fma(xp, a1.x, b1.x); acc[pp][2] = f2fma(xp, t, acc[pp][2]);
                t = f2fma(xp, a1.y, b1.y); acc[pp][3] = f2fma(xp, t, acc[pp][3]);
            }
        }
    }

    // epilogue: quad-wide softmax
    #pragma unroll
    for(int pp=0;pp<8;pp++){
        int p = pbase + pg*8 + pp;
        float qa[8];
        #pragma unroll
        for(int q=0;q<4;q++){
            float2 f = up2(acc[pp][q]);
            qa[2*q]   = f.x + c_s[vg*8 + 2*q];
            qa[2*q+1] = f.y + c_s[vg*8 + 2*q+1];
        }
        float mn = qa[0];
        #pragma unroll
        for(int i=1;i<8;i++) mn = fminf(mn, qa[i]);
        mn = fminf(mn, __shfl_xor_sync(0xffffffffu, mn, 1));
        mn = fminf(mn, __shfl_xor_sync(0xffffffffu, mn, 2));
        float sum = 0.0f;
        #pragma unroll
        for(int i=0;i<8;i++){ float e = __expf(-0.5f*(qa[i]-mn)); qa[i]=e; sum+=e; }
        sum += __shfl_xor_sync(0xffffffffu, sum, 1);
        sum += __shfl_xor_sync(0xffffffffu, sum, 2);
        float inv = 1.0f / sum;
        float4* dst = (float4*)(g_Q + (size_t)p*VV + vg*8);
        dst[0] = make_float4(qa[0]*inv, qa[1]*inv, qa[2]*inv, qa[3]*inv);
        dst[1] = make_float4(qa[4]*inv, qa[5]*inv, qa[6]*inv, qa[7]*inv);
    }
}

// ---------------- kernel 1b: M = X^T Q partials, s = colsum(Q) ------------
// v3: block 256, thread owns d = tid. 512 points/block, grid 512.
// 32-point Q tiles, register double-buffered (1 float4/thread).
__global__ __launch_bounds__(256) void k_mpass(const float* __restrict__ X){
    __shared__ __align__(16) float qs[32*VV];    // 4 KB tile
    __shared__ float ssh[256*4];
    const int tid = threadIdx.x;
    const int pbase = blockIdx.x * 512;

    ull m[16];                                   // m[2j],m[2j+1] <-> v=4j..4j+3
    #pragma unroll
    for(int i=0;i<16;i++) m[i]=0;
    float svec[4] = {0.f,0.f,0.f,0.f};

    // thread's Q-tile slot: point pt=tid>>3, v-quad (tid&7)*4  (linear = tid*4)
    float4 qnext = ((const float4*)(g_Q + (size_t)pbase*VV))[tid];

    for(int it=0; it<16; it++){
        __syncthreads();                         // prior tile's reads done
        ((float4*)qs)[tid] = qnext;
        svec[0]+=qnext.x; svec[1]+=qnext.y; svec[2]+=qnext.z; svec[3]+=qnext.w;
        __syncthreads();
        if(it+1 < 16)
            qnext = ((const float4*)(g_Q + (size_t)(pbase + (it+1)*32)*VV))[tid];

        const float* xp = X + (size_t)(pbase + it*32)*DD + tid;
        #pragma unroll
        for(int pb=0; pb<32; pb+=8){
            float x[8];
            #pragma unroll
            for(int k=0;k<8;k++) x[k] = xp[(pb+k)*DD];   // coalesced, MLP 8
            #pragma unroll
            for(int k=0;k<8;k++){
                ull xa = pk2(x[k], x[k]);
                const ulonglong2* qrow = (const ulonglong2*)(qs + (pb+k)*VV); // warp-uniform -> broadcast
                #pragma unroll
                for(int j=0;j<8;j++){
                    ulonglong2 qq = qrow[j];
                    m[2*j  ] = f2fma(xa, qq.x, m[2*j  ]);
                    m[2*j+1] = f2fma(xa, qq.y, m[2*j+1]);
                }
            }
        }
    }
    float* mp = g_Mpart + (size_t)blockIdx.x*DD*VV + tid*VV;
    #pragma unroll
    for(int j=0;j<16;j++){
        float2 f = up2(m[j]); mp[2*j]=f.x; mp[2*j+1]=f.y;
    }
    // colsum partials: thread covered v = (tid&7)*4 .. +4 over its point rows
    ssh[tid*4+0]=svec[0]; ssh[tid*4+1]=svec[1]; ssh[tid*4+2]=svec[2]; ssh[tid*4+3]=svec[3];
    __syncthreads();
    if(tid < VV){
        int v = tid, vq = v >> 2, i = v & 3;
        float s = 0.0f;
        #pragma unroll
        for(int g=0; g<32; g++) s += ssh[((g<<3) | vq)*4 + i];
        g_spart[blockIdx.x*VV + v] = s;
    }
}

// ---------------- kernel 2a: deterministic reduction ----------------------
__global__ void k_reduce(){
    if(blockIdx.x < 32){
        int e = blockIdx.x*256 + threadIdx.x;
        float s = 0.0f;
        for(int part=0; part<NPART; part++) s += g_Mpart[(size_t)part*DD*VV + e];
        g_M[e] = s;
    } else if(threadIdx.x < VV){
        float s = 0.0f;
        for(int part=0; part<NPART; part++) s += g_spart[part*VV + threadIdx.x];
        g_s[threadIdx.x] = s;
    }
}

// ---------------- kernel 2b: Z, normalize, Adj = Z^T Z --------------------
__global__ __launch_bounds__(256) void k_z(const float* __restrict__ W,
                                           const float* __restrict__ var){
    __shared__ float Zs[DD*33];
    __shared__ float s_s[VV], cs[VV];
    const int tid = threadIdx.x;
    if(tid < VV) s_s[tid] = g_s[tid];
    __syncthreads();

    #pragma unroll
    for(int v=0; v<VV; v++){
        int e = tid*VV + v;
        float sv = s_s[v];
        float z = (g_M[e] - W[e]*sv) * (1.0f/var[e]) / sv;
        Zs[tid*33 + v] = z;
    }
    __syncthreads();
    if(tid < VV){
        float acc = 0.0f;
        for(int d=0; d<DD; d++){ float z = Zs[d*33+tid]; acc = fmaf(z,z,acc); }
        cs[tid] = acc;
    }
    __syncthreads();
    #pragma unroll
    for(int v=0; v<VV; v++){
        float z = Zs[tid*33 + v] / cs[v];
        Zs[tid*33 + v] = z;
        g_Z[tid*VV + v] = z;
    }
    __syncthreads();
    for(int k=0;k<4;k++){
        int e = k*256 + tid;
        int i = e >> 5, j = e & 31;
        float acc = 0.0f;
        for(int d=0; d<DD; d++) acc = fmaf(Zs[d*33+i], Zs[d*33+j], acc);
        g_Adj[e] = acc;
    }
}

// ---------------- kernel 2c/2d: T1, Zo ------------------------------------
__global__ void k_t1(const float* __restrict__ weight){
    int v = blockIdx.x, f = threadIdx.x;
    float acc = 0.0f;
    for(int d=0; d<DD; d++) acc = fmaf(g_Z[d*VV+v], weight[d*NF+f], acc);
    g_T1[v*NF + f] = acc;
}
__global__ void k_zo(){
    int v = blockIdx.x, f = threadIdx.x;
    float acc = 0.0f;
    #pragma unroll
    for(int j=0;j<VV;j++) acc = fmaf(g_Adj[v*VV+j], g_T1[j*NF+f], acc);
    g_Zo[v*NF + f] = fmaxf(acc, 0.0f);
}

// ---------------- kernel 3: Xn = Q @ Zo -> out ----------------------------
__global__ __launch_bounds__(256) void k_out(float* __restrict__ out){
    __shared__ __align__(16) float zo[VV*NF];
    __shared__ __align__(16) float qts[8][264];

    const int tid = threadIdx.x, w = tid >> 5, l = tid & 31;
    for(int i=tid; i<VV*NF; i+=256) zo[i] = g_Zo[i];
    __syncthreads();

    const int pbase = blockIdx.x*64 + w*8;
    {
        const float4* src = (const float4*)(g_Q + (size_t)(pbase + (l>>2))*VV + (l&3)*8);
        float4 a = src[0], b = src[1];
        int p = l >> 2, vb = (l & 3)*8;
        float* dst = qts[w];
        dst[(vb+0)*8+p]=a.x; dst[(vb+1)*8+p]=a.y; dst[(vb+2)*8+p]=a.z; dst[(vb+3)*8+p]=a.w;
        dst[(vb+4)*8+p]=b.x; dst[(vb+5)*8+p]=b.y; dst[(vb+6)*8+p]=b.z; dst[(vb+7)*8+p]=b.w;
    }
    __syncwarp();

    ull acc[8][4];
    #pragma unroll
    for(int p=0;p<8;p++){ acc[p][0]=0; acc[p][1]=0; acc[p][2]=0; acc[p][3]=0; }

    #pragma unroll 4
    for(int v=0; v<VV; v++){
        ulonglong2 zA = *(const ulonglong2*)(zo + v*NF + l*4);
        ulonglong2 zB = *(const ulonglong2*)(zo + v*NF + 128 + l*4);
        const float* qv = qts[w] + v*8;
        float4 qA = *(const float4*)(qv);
        float4 qB = *(const float4*)(qv+4);
        float qf[8] = {qA.x,qA.y,qA.z,qA.w,qB.x,qB.y,qB.z,qB.w};
        #pragma unroll
        for(int p=0;p<8;p++){
            ull qp = pk2(qf[p], qf[p]);
            acc[p][0] = f2fma(qp, zA.x, acc[p][0]);
            acc[p][1] = f2fma(qp, zA.y, acc[p][1]);
            acc[p][2] = f2fma(qp, zB.x, acc[p][2]);
            acc[p][3] = f2fma(qp, zB.y, acc[p][3]);
        }
    }
    #pragma unroll
    for(int p=0;p<8;p++){
        float2 f0=up2(acc[p][0]), f1=up2(acc[p][1]);
        float2 f2v=up2(acc[p][2]), f3=up2(acc[p][3]);
        float* base = out + (size_t)(pbase+p)*NF;
        *(float4*)(base + l*4)       = make_float4(f0.x,f0.y,f1.x,f1.y);
        *(float4*)(base + 128 + l*4) = make_float4(f2v.x,f2v.y,f3.x,f3.y);
    }
}

// ---------------- launch ---------------------------------------------------
extern "C" void kernel_launch(void* const* d_in, const int* in_sizes, int n_in,
                              void* d_out, int out_size){
    const float* X      = (const float*)d_in[0];
    const float* W      = (const float*)d_in[1];
    const float* var    = (const float*)d_in[2];
    const float* weight = (const float*)d_in[3];
    float* out = (float*)d_out;

    static int smem_set = 0;
    const int qp_smem = (512*33 + 2048 + 32) * 4;
    if(!smem_set){
        cudaFuncSetAttribute(k_qpass, cudaFuncAttributeMaxDynamicSharedMemorySize, qp_smem);
        smem_set = 1;
    }

    k_prep  <<<32, 256>>>(W, var);
    k_prep_c<<<1, 32>>>(W);
    k_qpass <<<HW/512, 256, qp_smem>>>(X);
    k_mpass <<<NPART, 256>>>(X);
    k_reduce<<<33, 256>>>();
    k_z     <<<1, 256>>>(W, var);
    k_t1    <<<VV, 256>>>(weight);
    k_zo    <<<VV, 256>>>();
    k_out   <<<HW/64, 256>>>(out);
}

// round 8
// speedup vs baseline: 1.2363x; 1.0949x over previous
#include <cuda_runtime.h>
#include <math.h>

#define HW   262144
#define DD   256
#define VV   32
#define NF   256
#define NPART 512          // mpass blocks
#define NPARTS2 1024       // partials (2 per block)

// ---------------- scratch (device globals) --------------------------------
__device__ float g_iv2[DD*VV];
__device__ float g_nw2[DD*VV];      // -2 * W * iv2
__device__ float g_c[VV];           // sum_d W^2 * iv2
__device__ float g_Q[HW*VV];        // 32 MB
__device__ float g_Mpart[NPARTS2*DD*VV];   // 32 MB
__device__ float g_spart[NPARTS2*VV];
__device__ float g_M[DD*VV];
__device__ float g_s[VV];
__device__ float g_Z[DD*VV];
__device__ float g_Adj[VV*VV];
__device__ float g_T1[VV*NF];
__device__ float g_Zo[VV*NF];

// ---------------- packed f32x2 helpers -----------------------------------
typedef unsigned long long ull;
__device__ __forceinline__ ull pk2(float lo, float hi){
    ull r; asm("mov.b64 %0,{%1,%2};" : "=l"(r) : "f"(lo), "f"(hi)); return r;
}
__device__ __forceinline__ float2 up2(ull v){
    float2 r; asm("mov.b64 {%0,%1},%2;" : "=f"(r.x), "=f"(r.y) : "l"(v)); return r;
}
__device__ __forceinline__ ull f2fma(ull a, ull b, ull c){
    ull d; asm("fma.rn.f32x2 %0,%1,%2,%3;" : "=l"(d) : "l"(a), "l"(b), "l"(c)); return d;
}

// ---------------- kernel 0: precompute tables ----------------------------
__global__ void k_prep(const float* __restrict__ W, const float* __restrict__ var){
    int e = blockIdx.x*256 + threadIdx.x;
    float iv  = 1.0f / var[e];
    float iv2 = iv*iv;
    g_iv2[e] = iv2;
    g_nw2[e] = -2.0f * W[e] * iv2;
}
__global__ void k_prep_c(const float* __restrict__ W){
    int v = threadIdx.x;
    float c = 0.0f;
    for(int d=0; d<DD; d++){
        float w = W[d*VV+v];
        c = fmaf(w*w, g_iv2[d*VV+v], c);
    }
    g_c[v] = c;
}

// ---------------- kernel 1a: Q pass (fused 2 GEMMs + softmax) -------------
// unchanged (passing, near its SIMT floor)
__global__ __launch_bounds__(256, 2) void k_qpass(const float* __restrict__ X){
    extern __shared__ float sm[];
    float* xs  = sm;                 // 512*33
    float* ivc = sm + 512*33;        // 32*32
    float* nwc = ivc + 1024;         // 32*32
    float* c_s = nwc + 1024;         // 32

    const int tid = threadIdx.x;
    const int vg = tid & 3, pg = tid >> 2;
    const int pbase = blockIdx.x * 512;
    if(tid < VV) c_s[tid] = g_c[tid];

    ull acc[8][4];
    #pragma unroll
    for(int pp=0;pp<8;pp++){ acc[pp][0]=0; acc[pp][1]=0; acc[pp][2]=0; acc[pp][3]=0; }

    for(int ch=0; ch<8; ch++){
        __syncthreads();
        {
            float4 a = ((const float4*)(g_iv2 + ch*1024))[tid];
            ((float4*)ivc)[tid] = a;
            float4 b = ((const float4*)(g_nw2 + ch*1024))[tid];
            ((float4*)nwc)[tid] = b;
        }
        #pragma unroll
        for(int i=tid; i<512*8; i+=256){
            int pl = i >> 3, dq = (i & 7) * 4;
            float4 v = *(const float4*)(X + (size_t)(pbase+pl)*DD + ch*32 + dq);
            float* dst = xs + pl*33 + dq;
            dst[0]=v.x; dst[1]=v.y; dst[2]=v.z; dst[3]=v.w;
        }
        __syncthreads();

        const float* xrow = xs + pg*8*33;
        #pragma unroll 2
        for(int d=0; d<32; d++){
            const ulonglong2* ap = (const ulonglong2*)(ivc + d*32 + vg*8);
            const ulonglong2* bp = (const ulonglong2*)(nwc + d*32 + vg*8);
            ulonglong2 a0 = ap[0], a1 = ap[1];
            ulonglong2 b0 = bp[0], b1 = bp[1];
            float xv[8];
            #pragma unroll
            for(int pp=0;pp<8;pp++) xv[pp] = xrow[pp*33 + d];
            #pragma unroll
            for(int pp=0;pp<8;pp++){
                ull xp = pk2(xv[pp], xv[pp]);
                ull t;
                t = f2fma(xp, a0.x, b0.x); acc[pp][0] = f2fma(xp, t, acc[pp][0]);
                t = f2fma(xp, a0.y, b0.y); acc[pp][1] = f2fma(xp, t, acc[pp][1]);
                t = f2fma(xp, a1.x, b1.x); acc[pp][2] = f2fma(xp, t, acc[pp][2]);
                t = f2fma(xp, a1.y, b1.y); acc[pp][3] = f2fma(xp, t, acc[pp][3]);
            }
        }
    }

    #pragma unroll
    for(int pp=0;pp<8;pp++){
        int p = pbase + pg*8 + pp;
        float qa[8];
        #pragma unroll
        for(int q=0;q<4;q++){
            float2 f = up2(acc[pp][q]);
            qa[2*q]   = f.x + c_s[vg*8 + 2*q];
            qa[2*q+1] = f.y + c_s[vg*8 + 2*q+1];
        }
        float mn = qa[0];
        #pragma unroll
        for(int i=1;i<8;i++) mn = fminf(mn, qa[i]);
        mn = fminf(mn, __shfl_xor_sync(0xffffffffu, mn, 1));
        mn = fminf(mn, __shfl_xor_sync(0xffffffffu, mn, 2));
        float sum = 0.0f;
        #pragma unroll
        for(int i=0;i<8;i++){ float e = __expf(-0.5f*(qa[i]-mn)); qa[i]=e; sum+=e; }
        sum += __shfl_xor_sync(0xffffffffu, sum, 1);
        sum += __shfl_xor_sync(0xffffffffu, sum, 2);
        float inv = 1.0f / sum;
        float4* dst = (float4*)(g_Q + (size_t)p*VV + vg*8);
        dst[0] = make_float4(qa[0]*inv, qa[1]*inv, qa[2]*inv, qa[3]*inv);
        dst[1] = make_float4(qa[4]*inv, qa[5]*inv, qa[6]*inv, qa[7]*inv);
    }
}

// ---------------- kernel 1b: M = X^T Q partials, s = colsum(Q) ------------
// v4: block 256 split into 2 point-halves of 128 threads; each thread owns
// d = (tid&127)*2 .. +2 and 256 points. Q-row LDS amortized over 2 d.
__global__ __launch_bounds__(256, 2) void k_mpass(const float* __restrict__ X){
    __shared__ __align__(16) float qs[2][32*VV]; // 4 KB per half
    __shared__ float ssh[256*8];
    const int tid  = threadIdx.x;
    const int half = tid >> 7;                   // 0/1
    const int lt   = tid & 127;
    const int d0   = lt * 2;
    const int pbase = blockIdx.x * 512 + half * 256;

    ull m[32];   // m[k] (k<16): d0, v=2k..2k+1 ; m[16+k]: d0+1
    #pragma unroll
    for(int i=0;i<32;i++) m[i]=0;
    float svec[8];
    #pragma unroll
    for(int i=0;i<8;i++) svec[i]=0.0f;

    // prefetch first Q tile: each of 128 threads stages 2 float4 (32pts x 32v)
    const float4* qsrc = (const float4*)(g_Q + (size_t)pbase*VV);
    float4 qn0 = qsrc[lt*2], qn1 = qsrc[lt*2+1];

    for(int it=0; it<8; it++){                   // 8 tiles x 32 pts = 256 pts
        __syncthreads();
        ((float4*)qs[half])[lt*2]   = qn0;
        ((float4*)qs[half])[lt*2+1] = qn1;
        svec[0]+=qn0.x; svec[1]+=qn0.y; svec[2]+=qn0.z; svec[3]+=qn0.w;
        svec[4]+=qn1.x; svec[5]+=qn1.y; svec[6]+=qn1.z; svec[7]+=qn1.w;
        __syncthreads();
        if(it+1 < 8){
            const float4* qn = (const float4*)(g_Q + (size_t)(pbase + (it+1)*32)*VV);
            qn0 = qn[lt*2]; qn1 = qn[lt*2+1];
        }

        const float* xp = X + (size_t)(pbase + it*32)*DD + d0;
        #pragma unroll
        for(int pb=0; pb<32; pb+=8){
            float2 x[8];
            #pragma unroll
            for(int k=0;k<8;k++) x[k] = *(const float2*)(xp + (pb+k)*DD);
            #pragma unroll
            for(int k=0;k<8;k++){
                ull xa = pk2(x[k].x, x[k].x);
                ull xb = pk2(x[k].y, x[k].y);
                const ulonglong2* qrow = (const ulonglong2*)(qs[half] + (pb+k)*VV);
                #pragma unroll
                for(int j=0;j<8;j++){
                    ulonglong2 qq = qrow[j];
                    m[2*j   ]  = f2fma(xa, qq.x, m[2*j   ]);
                    m[2*j+1 ]  = f2fma(xa, qq.y, m[2*j+1 ]);
                    m[16+2*j]  = f2fma(xb, qq.x, m[16+2*j]);
                    m[16+2*j+1]= f2fma(xb, qq.y, m[16+2*j+1]);
                }
            }
        }
    }
    // store partials: partial index = blockIdx.x*2 + half
    float* mp = g_Mpart + (size_t)(blockIdx.x*2 + half)*DD*VV + d0*VV;
    #pragma unroll
    for(int j=0;j<16;j++){
        float2 f = up2(m[j]);    mp[2*j]    = f.x; mp[2*j+1]    = f.y;   // d0
    }
    #pragma unroll
    for(int j=0;j<16;j++){
        float2 f = up2(m[16+j]); mp[VV+2*j] = f.x; mp[VV+2*j+1] = f.y;   // d0+1
    }
    // colsum partials: thread lt covered v = (lt&3)*8 .. +8 for pts lt>>2 of each tile
    #pragma unroll
    for(int i=0;i<8;i++) ssh[tid*8+i] = svec[i];
    __syncthreads();
    if(tid < 2*VV){
        int h = tid >> 5, v = tid & 31;
        float s = 0.0f;
        #pragma unroll
        for(int g=0; g<32; g++) s += ssh[(h*128 + g*4 + (v>>3))*8 + (v&7)];
        g_spart[(blockIdx.x*2 + h)*VV + v] = s;
    }
}

// ---------------- kernel 2a: deterministic reduction ----------------------
__global__ void k_reduce(){
    if(blockIdx.x < 32){
        int e = blockIdx.x*256 + threadIdx.x;
        float s0=0.f, s1=0.f, s2=0.f, s3=0.f;
        for(int part=0; part<NPARTS2; part+=4){
            s0 += g_Mpart[(size_t)(part  )*DD*VV + e];
            s1 += g_Mpart[(size_t)(part+1)*DD*VV + e];
            s2 += g_Mpart[(size_t)(part+2)*DD*VV + e];
            s3 += g_Mpart[(size_t)(part+3)*DD*VV + e];
        }
        g_M[e] = (s0+s1)+(s2+s3);
    } else if(threadIdx.x < VV){
        float s = 0.0f;
        for(int part=0; part<NPARTS2; part++) s += g_spart[part*VV + threadIdx.x];
        g_s[threadIdx.x] = s;
    }
}

// ---------------- kernel 2b: Z, normalize, Adj = Z^T Z --------------------
__global__ __launch_bounds__(256) void k_z(const float* __restrict__ W,
                                           const float* __restrict__ var){
    __shared__ float Zs[DD*33];
    __shared__ float s_s[VV], cs[VV];
    const int tid = threadIdx.x;
    if(tid < VV) s_s[tid] = g_s[tid];
    __syncthreads();

    #pragma unroll
    for(int v=0; v<VV; v++){
        int e = tid*VV + v;
        float sv = s_s[v];
        float z = (g_M[e] - W[e]*sv) * (1.0f/var[e]) / sv;
        Zs[tid*33 + v] = z;
    }
    __syncthreads();
    if(tid < VV){
        float acc = 0.0f;
        for(int d=0; d<DD; d++){ float z = Zs[d*33+tid]; acc = fmaf(z,z,acc); }
        cs[tid] = acc;
    }
    __syncthreads();
    #pragma unroll
    for(int v=0; v<VV; v++){
        float z = Zs[tid*33 + v] / cs[v];
        Zs[tid*33 + v] = z;
        g_Z[tid*VV + v] = z;
    }
    __syncthreads();
    for(int k=0;k<4;k++){
        int e = k*256 + tid;
        int i = e >> 5, j = e & 31;
        float acc = 0.0f;
        for(int d=0; d<DD; d++) acc = fmaf(Zs[d*33+i], Zs[d*33+j], acc);
        g_Adj[e] = acc;
    }
}

// ---------------- kernel 2c/2d: T1, Zo ------------------------------------
__global__ void k_t1(const float* __restrict__ weight){
    int v = blockIdx.x, f = threadIdx.x;
    float acc = 0.0f;
    for(int d=0; d<DD; d++) acc = fmaf(g_Z[d*VV+v], weight[d*NF+f], acc);
    g_T1[v*NF + f] = acc;
}
__global__ void k_zo(){
    int v = blockIdx.x, f = threadIdx.x;
    float acc = 0.0f;
    #pragma unroll
    for(int j=0;j<VV;j++) acc = fmaf(g_Adj[v*VV+j], g_T1[j*NF+f], acc);
    g_Zo[v*NF + f] = fmaxf(acc, 0.0f);
}

// ---------------- kernel 3: Xn = Q @ Zo -> out ----------------------------
__global__ __launch_bounds__(256) void k_out(float* __restrict__ out){
    __shared__ __align__(16) float zo[VV*NF];
    __shared__ __align__(16) float qts[8][264];

    const int tid = threadIdx.x, w = tid >> 5, l = tid & 31;
    for(int i=tid; i<VV*NF; i+=256) zo[i] = g_Zo[i];
    __syncthreads();

    const int pbase = blockIdx.x*64 + w*8;
    {
        const float4* src = (const float4*)(g_Q + (size_t)(pbase + (l>>2))*VV + (l&3)*8);
        float4 a = src[0], b = src[1];
        int p = l >> 2, vb = (l & 3)*8;
        float* dst = qts[w];
        dst[(vb+0)*8+p]=a.x; dst[(vb+1)*8+p]=a.y; dst[(vb+2)*8+p]=a.z; dst[(vb+3)*8+p]=a.w;
        dst[(vb+4)*8+p]=b.x; dst[(vb+5)*8+p]=b.y; dst[(vb+6)*8+p]=b.z; dst[(vb+7)*8+p]=b.w;
    }
    __syncwarp();

    ull acc[8][4];
    #pragma unroll
    for(int p=0;p<8;p++){ acc[p][0]=0; acc[p][1]=0; acc[p][2]=0; acc[p][3]=0; }

    #pragma unroll 4
    for(int v=0; v<VV; v++){
        ulonglong2 zA = *(const ulonglong2*)(zo + v*NF + l*4);
        ulonglong2 zB = *(const ulonglong2*)(zo + v*NF + 128 + l*4);
        const float* qv = qts[w] + v*8;
        float4 qA = *(const float4*)(qv);
        float4 qB = *(const float4*)(qv+4);
        float qf[8] = {qA.x,qA.y,qA.z,qA.w,qB.x,qB.y,qB.z,qB.w};
        #pragma unroll
        for(int p=0;p<8;p++){
            ull qp = pk2(qf[p], qf[p]);
            acc[p][0] = f2fma(qp, zA.x, acc[p][0]);
            acc[p][1] = f2fma(qp, zA.y, acc[p][1]);
            acc[p][2] = f2fma(qp, zB.x, acc[p][2]);
            acc[p][3] = f2fma(qp, zB.y, acc[p][3]);
        }
    }
    #pragma unroll
    for(int p=0;p<8;p++){
        float2 f0=up2(acc[p][0]), f1=up2(acc[p][1]);
        float2 f2v=up2(acc[p][2]), f3=up2(acc[p][3]);
        float* base = out + (size_t)(pbase+p)*NF;
        *(float4*)(base + l*4)       = make_float4(f0.x,f0.y,f1.x,f1.y);
        *(float4*)(base + 128 + l*4) = make_float4(f2v.x,f2v.y,f3.x,f3.y);
    }
}

// ---------------- launch ---------------------------------------------------
extern "C" void kernel_launch(void* const* d_in, const int* in_sizes, int n_in,
                              void* d_out, int out_size){
    const float* X      = (const float*)d_in[0];
    const float* W      = (const float*)d_in[1];
    const float* var    = (const float*)d_in[2];
    const float* weight = (const float*)d_in[3];
    float* out = (float*)d_out;

    static int smem_set = 0;
    const int qp_smem = (512*33 + 2048 + 32) * 4;
    if(!smem_set){
        cudaFuncSetAttribute(k_qpass, cudaFuncAttributeMaxDynamicSharedMemorySize, qp_smem);
        smem_set = 1;
    }

    k_prep  <<<32, 256>>>(W, var);
    k_prep_c<<<1, 32>>>(W);
    k_qpass <<<HW/512, 256, qp_smem>>>(X);
    k_mpass <<<NPART, 256>>>(X);
    k_reduce<<<33, 256>>>();
    k_z     <<<1, 256>>>(W, var);
    k_t1    <<<VV, 256>>>(weight);
    k_zo    <<<VV, 256>>>();
    k_out   <<<HW/64, 256>>>(out);
}

// round 9
// speedup vs baseline: 1.3786x; 1.1152x over previous
#include <cuda_runtime.h>
#include <math.h>

#define HW   262144
#define DD   256
#define VV   32
#define NF   256
#define NPART 512          // mpass blocks
#define NPARTS2 1024       // partials (2 per block)

// ---------------- scratch (device globals) --------------------------------
__device__ float g_iv2[DD*VV];
__device__ float g_nw2[DD*VV];      // -2 * W * iv2
__device__ float g_c[VV];           // sum_d W^2 * iv2
__device__ float g_Q[HW*VV];        // 32 MB
__device__ float g_Mpart[NPARTS2*DD*VV];   // 32 MB
__device__ float g_spart[NPARTS2*VV];
__device__ float g_M2[16*DD*VV];    // stage-A partial sums
__device__ float g_M[DD*VV];
__device__ float g_s[VV];
__device__ float g_Z[DD*VV];
__device__ float g_Adj[VV*VV];
__device__ float g_T1[VV*NF];
__device__ float g_Zo[VV*NF];

// ---------------- packed f32x2 helpers -----------------------------------
typedef unsigned long long ull;
__device__ __forceinline__ ull pk2(float lo, float hi){
    ull r; asm("mov.b64 %0,{%1,%2};" : "=l"(r) : "f"(lo), "f"(hi)); return r;
}
__device__ __forceinline__ float2 up2(ull v){
    float2 r; asm("mov.b64 {%0,%1},%2;" : "=f"(r.x), "=f"(r.y) : "l"(v)); return r;
}
__device__ __forceinline__ ull f2fma(ull a, ull b, ull c){
    ull d; asm("fma.rn.f32x2 %0,%1,%2,%3;" : "=l"(d) : "l"(a), "l"(b), "l"(c)); return d;
}

// ---------------- kernel 0: precompute tables ----------------------------
__global__ void k_prep(const float* __restrict__ W, const float* __restrict__ var){
    int e = blockIdx.x*256 + threadIdx.x;
    float iv  = 1.0f / var[e];
    float iv2 = iv*iv;
    g_iv2[e] = iv2;
    g_nw2[e] = -2.0f * W[e] * iv2;
}
__global__ void k_prep_c(const float* __restrict__ W){
    int v = threadIdx.x;
    float c = 0.0f;
    for(int d=0; d<DD; d++){
        float w = W[d*VV+v];
        c = fmaf(w*w, g_iv2[d*VV+v], c);
    }
    g_c[v] = c;
}

// ---------------- kernel 1a: Q pass v3 ------------------------------------
// Full tables resident in smem (64KB, loaded once, barrier-free mainloop).
// X read directly via LDG.128: each point's 32-d chunk row = one L1 line,
// shared by its 4-lane quad. quad: vg=tid&3 owns v=vg*8..+8; pg=tid>>2 owns
// points pg*8..+8. 512 points/block, grid 512.
__global__ __launch_bounds__(256, 2) void k_qpass(const float* __restrict__ X){
    extern __shared__ float sm[];
    float* ivc = sm;                 // 8192
    float* nwc = sm + DD*VV;         // 8192
    float* c_s = nwc + DD*VV;        // 32

    const int tid = threadIdx.x;
    const int vg = tid & 3, pg = tid >> 2;
    const int pbase = blockIdx.x * 512;

    #pragma unroll
    for(int i=tid; i<DD*VV/4; i+=256){
        ((float4*)ivc)[i] = ((const float4*)g_iv2)[i];
        ((float4*)nwc)[i] = ((const float4*)g_nw2)[i];
    }
    if(tid < VV) c_s[tid] = g_c[tid];
    __syncthreads();

    ull acc[8][4];
    #pragma unroll
    for(int pp=0;pp<8;pp++){ acc[pp][0]=0; acc[pp][1]=0; acc[pp][2]=0; acc[pp][3]=0; }

    const float* xbase = X + (size_t)(pbase + pg*8)*DD;

    for(int c=0; c<64; c++){                     // d-quad index, d = 4c..4c+3
        float4 xv[8];
        #pragma unroll
        for(int pp=0;pp<8;pp++)
            xv[pp] = *(const float4*)(xbase + pp*DD + c*4);   // L1-hot
        #pragma unroll
        for(int dd=0; dd<4; dd++){
            const int d = c*4 + dd;
            const ulonglong2* ap = (const ulonglong2*)(ivc + d*32 + vg*8);
            const ulonglong2* bp = (const ulonglong2*)(nwc + d*32 + vg*8);
            ulonglong2 a0 = ap[0], a1 = ap[1];
            ulonglong2 b0 = bp[0], b1 = bp[1];
            #pragma unroll
            for(int pp=0;pp<8;pp++){
                float x = (dd==0) ? xv[pp].x : (dd==1) ? xv[pp].y
                        : (dd==2) ? xv[pp].z : xv[pp].w;
                ull xp = pk2(x, x);
                ull t;
                t = f2fma(xp, a0.x, b0.x); acc[pp][0] = f2fma(xp, t, acc[pp][0]);
                t = f2fma(xp, a0.y, b0.y); acc[pp][1] = f2fma(xp, t, acc[pp][1]);
                t = f2fma(xp, a1.x, b1.x); acc[pp][2] = f2fma(xp, t, acc[pp][2]);
                t = f2fma(xp, a1.y, b1.y); acc[pp][3] = f2fma(xp, t, acc[pp][3]);
            }
        }
    }

    // epilogue: quad-wide softmax (unchanged)
    #pragma unroll
    for(int pp=0;pp<8;pp++){
        int p = pbase + pg*8 + pp;
        float qa[8];
        #pragma unroll
        for(int q=0;q<4;q++){
            float2 f = up2(acc[pp][q]);
            qa[2*q]   = f.x + c_s[vg*8 + 2*q];
            qa[2*q+1] = f.y + c_s[vg*8 + 2*q+1];
        }
        float mn = qa[0];
        #pragma unroll
        for(int i=1;i<8;i++) mn = fminf(mn, qa[i]);
        mn = fminf(mn, __shfl_xor_sync(0xffffffffu, mn, 1));
        mn = fminf(mn, __shfl_xor_sync(0xffffffffu, mn, 2));
        float sum = 0.0f;
        #pragma unroll
        for(int i=0;i<8;i++){ float e = __expf(-0.5f*(qa[i]-mn)); qa[i]=e; sum+=e; }
        sum += __shfl_xor_sync(0xffffffffu, sum, 1);
        sum += __shfl_xor_sync(0xffffffffu, sum, 2);
        float inv = 1.0f / sum;
        float4* dst = (float4*)(g_Q + (size_t)p*VV + vg*8);
        dst[0] = make_float4(qa[0]*inv, qa[1]*inv, qa[2]*inv, qa[3]*inv);
        dst[1] = make_float4(qa[4]*inv, qa[5]*inv, qa[6]*inv, qa[7]*inv);
    }
}

// ---------------- kernel 1b: M = X^T Q partials, s = colsum(Q) ------------
// (unchanged from round 8 — measured 153us)
__global__ __launch_bounds__(256, 2) void k_mpass(const float* __restrict__ X){
    __shared__ __align__(16) float qs[2][32*VV];
    __shared__ float ssh[256*8];
    const int tid  = threadIdx.x;
    const int half = tid >> 7;
    const int lt   = tid & 127;
    const int d0   = lt * 2;
    const int pbase = blockIdx.x * 512 + half * 256;

    ull m[32];
    #pragma unroll
    for(int i=0;i<32;i++) m[i]=0;
    float svec[8];
    #pragma unroll
    for(int i=0;i<8;i++) svec[i]=0.0f;

    const float4* qsrc = (const float4*)(g_Q + (size_t)pbase*VV);
    float4 qn0 = qsrc[lt*2], qn1 = qsrc[lt*2+1];

    for(int it=0; it<8; it++){
        __syncthreads();
        ((float4*)qs[half])[lt*2]   = qn0;
        ((float4*)qs[half])[lt*2+1] = qn1;
        svec[0]+=qn0.x; svec[1]+=qn0.y; svec[2]+=qn0.z; svec[3]+=qn0.w;
        svec[4]+=qn1.x; svec[5]+=qn1.y; svec[6]+=qn1.z; svec[7]+=qn1.w;
        __syncthreads();
        if(it+1 < 8){
            const float4* qn = (const float4*)(g_Q + (size_t)(pbase + (it+1)*32)*VV);
            qn0 = qn[lt*2]; qn1 = qn[lt*2+1];
        }

        const float* xp = X + (size_t)(pbase + it*32)*DD + d0;
        #pragma unroll
        for(int pb=0; pb<32; pb+=8){
            float2 x[8];
            #pragma unroll
            for(int k=0;k<8;k++) x[k] = *(const float2*)(xp + (pb+k)*DD);
            #pragma unroll
            for(int k=0;k<8;k++){
                ull xa = pk2(x[k].x, x[k].x);
                ull xb = pk2(x[k].y, x[k].y);
                const ulonglong2* qrow = (const ulonglong2*)(qs[half] + (pb+k)*VV);
                #pragma unroll
                for(int j=0;j<8;j++){
                    ulonglong2 qq = qrow[j];
                    m[2*j   ]  = f2fma(xa, qq.x, m[2*j   ]);
                    m[2*j+1 ]  = f2fma(xa, qq.y, m[2*j+1 ]);
                    m[16+2*j]  = f2fma(xb, qq.x, m[16+2*j]);
                    m[16+2*j+1]= f2fma(xb, qq.y, m[16+2*j+1]);
                }
            }
        }
    }
    float* mp = g_Mpart + (size_t)(blockIdx.x*2 + half)*DD*VV + d0*VV;
    #pragma unroll
    for(int j=0;j<16;j++){
        float2 f = up2(m[j]);    mp[2*j]    = f.x; mp[2*j+1]    = f.y;
    }
    #pragma unroll
    for(int j=0;j<16;j++){
        float2 f = up2(m[16+j]); mp[VV+2*j] = f.x; mp[VV+2*j+1] = f.y;
    }
    #pragma unroll
    for(int i=0;i<8;i++) ssh[tid*8+i] = svec[i];
    __syncthreads();
    if(tid < 2*VV){
        int h = tid >> 5, v = tid & 31;
        float s = 0.0f;
        #pragma unroll
        for(int g=0; g<32; g++) s += ssh[(h*128 + g*4 + (v>>3))*8 + (v&7)];
        g_spart[(blockIdx.x*2 + h)*VV + v] = s;
    }
}

// ---------------- kernel 2a: two-stage deterministic reduction ------------
__global__ void k_reduceA(){
    int pg = blockIdx.x >> 5;            // 0..15  (part-group of 64)
    int ec = blockIdx.x & 31;            // 0..31
    int e  = ec*256 + threadIdx.x;
    const float* base = g_Mpart + (size_t)pg*64*DD*VV + e;
    float s0=0.f, s1=0.f, s2=0.f, s3=0.f;
    for(int p=0; p<64; p+=4){
        s0 += base[(size_t)(p  )*DD*VV];
        s1 += base[(size_t)(p+1)*DD*VV];
        s2 += base[(size_t)(p+2)*DD*VV];
        s3 += base[(size_t)(p+3)*DD*VV];
    }
    g_M2[pg*DD*VV + e] = (s0+s1)+(s2+s3);
}
__global__ void k_reduceB(){
    if(blockIdx.x < 32){
        int e = blockIdx.x*256 + threadIdx.x;
        float s = 0.0f;
        #pragma unroll
        for(int g=0; g<16; g++) s += g_M2[g*DD*VV + e];
        g_M[e] = s;
    } else {
        __shared__ float sh[256];
        int v = threadIdx.x & 31, grp = threadIdx.x >> 5;
        float s = 0.0f;
        for(int p=grp; p<NPARTS2; p+=8) s += g_spart[p*VV + v];
        sh[threadIdx.x] = s;
        __syncthreads();
        if(threadIdx.x < VV){
            float t = 0.0f;
            #pragma unroll
            for(int g=0; g<8; g++) t += sh[g*32 + threadIdx.x];
            g_s[threadIdx.x] = t;
        }
    }
}

// ---------------- kernel 2b: Z, normalize, Adj = Z^T Z --------------------
__global__ __launch_bounds__(256) void k_z(const float* __restrict__ W,
                                           const float* __restrict__ var){
    __shared__ float Zs[DD*33];
    __shared__ float s_s[VV], cs[VV];
    const int tid = threadIdx.x;
    if(tid < VV) s_s[tid] = g_s[tid];
    __syncthreads();

    #pragma unroll
    for(int v=0; v<VV; v++){
        int e = tid*VV + v;
        float sv = s_s[v];
        float z = (g_M[e] - W[e]*sv) * (1.0f/var[e]) / sv;
        Zs[tid*33 + v] = z;
    }
    __syncthreads();
    if(tid < VV){
        float acc = 0.0f;
        for(int d=0; d<DD; d++){ float z = Zs[d*33+tid]; acc = fmaf(z,z,acc); }
        cs[tid] = acc;
    }
    __syncthreads();
    #pragma unroll
    for(int v=0; v<VV; v++){
        float z = Zs[tid*33 + v] / cs[v];
        Zs[tid*33 + v] = z;
        g_Z[tid*VV + v] = z;
    }
    __syncthreads();
    for(int k=0;k<4;k++){
        int e = k*256 + tid;
        int i = e >> 5, j = e & 31;
        float acc = 0.0f;
        for(int d=0; d<DD; d++) acc = fmaf(Zs[d*33+i], Zs[d*33+j], acc);
        g_Adj[e] = acc;
    }
}

// ---------------- kernel 2c/2d: T1, Zo ------------------------------------
__global__ void k_t1(const float* __restrict__ weight){
    int v = blockIdx.x, f = threadIdx.x;
    float acc = 0.0f;
    for(int d=0; d<DD; d++) acc = fmaf(g_Z[d*VV+v], weight[d*NF+f], acc);
    g_T1[v*NF + f] = acc;
}
__global__ void k_zo(){
    int v = blockIdx.x, f = threadIdx.x;
    float acc = 0.0f;
    #pragma unroll
    for(int j=0;j<VV;j++) acc = fmaf(g_Adj[v*VV+j], g_T1[j*NF+f], acc);
    g_Zo[v*NF + f] = fmaxf(acc, 0.0f);
}

// ---------------- kernel 3: Xn = Q @ Zo -> out ----------------------------
__global__ __launch_bounds__(256) void k_out(float* __restrict__ out){
    __shared__ __align__(16) float zo[VV*NF];
    __shared__ __align__(16) float qts[8][264];

    const int tid = threadIdx.x, w = tid >> 5, l = tid & 31;
    for(int i=tid; i<VV*NF; i+=256) zo[i] = g_Zo[i];
    __syncthreads();

    const int pbase = blockIdx.x*64 + w*8;
    {
        const float4* src = (const float4*)(g_Q + (size_t)(pbase + (l>>2))*VV + (l&3)*8);
        float4 a = src[0], b = src[1];
        int p = l >> 2, vb = (l & 3)*8;
        float* dst = qts[w];
        dst[(vb+0)*8+p]=a.x; dst[(vb+1)*8+p]=a.y; dst[(vb+2)*8+p]=a.z; dst[(vb+3)*8+p]=a.w;
        dst[(vb+4)*8+p]=b.x; dst[(vb+5)*8+p]=b.y; dst[(vb+6)*8+p]=b.z; dst[(vb+7)*8+p]=b.w;
    }
    __syncwarp();

    ull acc[8][4];
    #pragma unroll
    for(int p=0;p<8;p++){ acc[p][0]=0; acc[p][1]=0; acc[p][2]=0; acc[p][3]=0; }

    #pragma unroll 4
    for(int v=0; v<VV; v++){
        ulonglong2 zA = *(const ulonglong2*)(zo + v*NF + l*4);
        ulonglong2 zB = *(const ulonglong2*)(zo + v*NF + 128 + l*4);
        const float* qv = qts[w] + v*8;
        float4 qA = *(const float4*)(qv);
        float4 qB = *(const float4*)(qv+4);
        float qf[8] = {qA.x,qA.y,qA.z,qA.w,qB.x,qB.y,qB.z,qB.w};
        #pragma unroll
        for(int p=0;p<8;p++){
            ull qp = pk2(qf[p], qf[p]);
            acc[p][0] = f2fma(qp, zA.x, acc[p][0]);
            acc[p][1] = f2fma(qp, zA.y, acc[p][1]);
            acc[p][2] = f2fma(qp, zB.x, acc[p][2]);
            acc[p][3] = f2fma(qp, zB.y, acc[p][3]);
        }
    }
    #pragma unroll
    for(int p=0;p<8;p++){
        float2 f0=up2(acc[p][0]), f1=up2(acc[p][1]);
        float2 f2v=up2(acc[p][2]), f3=up2(acc[p][3]);
        float* base = out + (size_t)(pbase+p)*NF;
        *(float4*)(base + l*4)       = make_float4(f0.x,f0.y,f1.x,f1.y);
        *(float4*)(base + 128 + l*4) = make_float4(f2v.x,f2v.y,f3.x,f3.y);
    }
}

// ---------------- launch ---------------------------------------------------
extern "C" void kernel_launch(void* const* d_in, const int* in_sizes, int n_in,
                              void* d_out, int out_size){
    const float* X      = (const float*)d_in[0];
    const float* W      = (const float*)d_in[1];
    const float* var    = (const float*)d_in[2];
    const float* weight = (const float*)d_in[3];
    float* out = (float*)d_out;

    static int smem_set = 0;
    const int qp_smem = (DD*VV*2 + 32) * 4;     // 65.7 KB
    if(!smem_set){
        cudaFuncSetAttribute(k_qpass, cudaFuncAttributeMaxDynamicSharedMemorySize, qp_smem);
        smem_set = 1;
    }

    k_prep   <<<32, 256>>>(W, var);
    k_prep_c <<<1, 32>>>(W);
    k_qpass  <<<HW/512, 256, qp_smem>>>(X);
    k_mpass  <<<NPART, 256>>>(X);
    k_reduceA<<<512, 256>>>();
    k_reduceB<<<33, 256>>>();
    k_z      <<<1, 256>>>(W, var);
    k_t1     <<<VV, 256>>>(weight);
    k_zo     <<<VV, 256>>>();
    k_out    <<<HW/64, 256>>>(out);
}

// round 11
// speedup vs baseline: 1.4413x; 1.0455x over previous
#include <cuda_runtime.h>
#include <math.h>

#define HW   262144
#define DD   256
#define VV   32
#define NF   256
#define NPART 512          // mpass blocks
#define NPARTS2 1024       // partials (2 per block)

// ---------------- scratch (device globals) --------------------------------
__device__ float g_iv2[DD*VV];
__device__ float g_nw2[DD*VV];      // -2 * W * iv2
__device__ float g_c[VV];           // sum_d W^2 * iv2
__device__ float g_Q[HW*VV];        // 32 MB
__device__ float g_Mpart[NPARTS2*DD*VV];   // 32 MB
__device__ float g_spart[NPARTS2*VV];
__device__ float g_M2[16*DD*VV];    // stage-A partial sums
__device__ float g_M[DD*VV];
__device__ float g_s[VV];
__device__ float g_Z[DD*VV];
__device__ float g_Adj[VV*VV];
__device__ float g_T1[VV*NF];
__device__ float g_Zo[VV*NF];

// ---------------- packed f32x2 helpers -----------------------------------
typedef unsigned long long ull;
__device__ __forceinline__ ull pk2(float lo, float hi){
    ull r; asm("mov.b64 %0,{%1,%2};" : "=l"(r) : "f"(lo), "f"(hi)); return r;
}
__device__ __forceinline__ float2 up2(ull v){
    float2 r; asm("mov.b64 {%0,%1},%2;" : "=f"(r.x), "=f"(r.y) : "l"(v)); return r;
}
__device__ __forceinline__ ull f2fma(ull a, ull b, ull c){
    ull d; asm("fma.rn.f32x2 %0,%1,%2,%3;" : "=l"(d) : "l"(a), "l"(b), "l"(c)); return d;
}

// ---------------- kernel 0: precompute tables ----------------------------
__global__ void k_prep(const float* __restrict__ W, const float* __restrict__ var){
    int e = blockIdx.x*256 + threadIdx.x;
    float iv  = 1.0f / var[e];
    float iv2 = iv*iv;
    g_iv2[e] = iv2;
    g_nw2[e] = -2.0f * W[e] * iv2;
}
__global__ void k_prep_c(const float* __restrict__ W){
    int v = threadIdx.x;
    float c = 0.0f;
    for(int d=0; d<DD; d++){
        float w = W[d*VV+v];
        c = fmaf(w*w, g_iv2[d*VV+v], c);
    }
    g_c[v] = c;
}

// ---------------- kernel 1a: Q pass v3 (unchanged, passing) ----------------
__global__ __launch_bounds__(256, 2) void k_qpass(const float* __restrict__ X){
    extern __shared__ float sm[];
    float* ivc = sm;
    float* nwc = sm + DD*VV;
    float* c_s = nwc + DD*VV;

    const int tid = threadIdx.x;
    const int vg = tid & 3, pg = tid >> 2;
    const int pbase = blockIdx.x * 512;

    #pragma unroll
    for(int i=tid; i<DD*VV/4; i+=256){
        ((float4*)ivc)[i] = ((const float4*)g_iv2)[i];
        ((float4*)nwc)[i] = ((const float4*)g_nw2)[i];
    }
    if(tid < VV) c_s[tid] = g_c[tid];
    __syncthreads();

    ull acc[8][4];
    #pragma unroll
    for(int pp=0;pp<8;pp++){ acc[pp][0]=0; acc[pp][1]=0; acc[pp][2]=0; acc[pp][3]=0; }

    const float* xbase = X + (size_t)(pbase + pg*8)*DD;

    for(int c=0; c<64; c++){
        float4 xv[8];
        #pragma unroll
        for(int pp=0;pp<8;pp++)
            xv[pp] = *(const float4*)(xbase + pp*DD + c*4);
        #pragma unroll
        for(int dd=0; dd<4; dd++){
            const int d = c*4 + dd;
            const ulonglong2* ap = (const ulonglong2*)(ivc + d*32 + vg*8);
            const ulonglong2* bp = (const ulonglong2*)(nwc + d*32 + vg*8);
            ulonglong2 a0 = ap[0], a1 = ap[1];
            ulonglong2 b0 = bp[0], b1 = bp[1];
            #pragma unroll
            for(int pp=0;pp<8;pp++){
                float x = (dd==0) ? xv[pp].x : (dd==1) ? xv[pp].y
                        : (dd==2) ? xv[pp].z : xv[pp].w;
                ull xp = pk2(x, x);
                ull t;
                t = f2fma(xp, a0.x, b0.x); acc[pp][0] = f2fma(xp, t, acc[pp][0]);
                t = f2fma(xp, a0.y, b0.y); acc[pp][1] = f2fma(xp, t, acc[pp][1]);
                t = f2fma(xp, a1.x, b1.x); acc[pp][2] = f2fma(xp, t, acc[pp][2]);
                t = f2fma(xp, a1.y, b1.y); acc[pp][3] = f2fma(xp, t, acc[pp][3]);
            }
        }
    }

    #pragma unroll
    for(int pp=0;pp<8;pp++){
        int p = pbase + pg*8 + pp;
        float qa[8];
        #pragma unroll
        for(int q=0;q<4;q++){
            float2 f = up2(acc[pp][q]);
            qa[2*q]   = f.x + c_s[vg*8 + 2*q];
            qa[2*q+1] = f.y + c_s[vg*8 + 2*q+1];
        }
        float mn = qa[0];
        #pragma unroll
        for(int i=1;i<8;i++) mn = fminf(mn, qa[i]);
        mn = fminf(mn, __shfl_xor_sync(0xffffffffu, mn, 1));
        mn = fminf(mn, __shfl_xor_sync(0xffffffffu, mn, 2));
        float sum = 0.0f;
        #pragma unroll
        for(int i=0;i<8;i++){ float e = __expf(-0.5f*(qa[i]-mn)); qa[i]=e; sum+=e; }
        sum += __shfl_xor_sync(0xffffffffu, sum, 1);
        sum += __shfl_xor_sync(0xffffffffu, sum, 2);
        float inv = 1.0f / sum;
        float4* dst = (float4*)(g_Q + (size_t)p*VV + vg*8);
        dst[0] = make_float4(qa[0]*inv, qa[1]*inv, qa[2]*inv, qa[3]*inv);
        dst[1] = make_float4(qa[4]*inv, qa[5]*inv, qa[6]*inv, qa[7]*inv);
    }
}

// ---------------- kernel 1b: M = X^T Q partials, s = colsum(Q) ------------
// v5: block 256 = 2 point-halves of 128 threads. Thread lt owns vh=lt&1
// (v = vh*16..+16) and dq=lt>>1 (d = dq*4..+4). Per point: 4 broadcast
// LDS.128 (q) + amortized coalesced LDG.128 (x) vs 32 f2fma.
__global__ __launch_bounds__(256, 2) void k_mpass(const float* __restrict__ X){
    __shared__ __align__(16) float qs[2][32*VV];
    __shared__ float ssh[256*8];
    const int tid  = threadIdx.x;
    const int half = tid >> 7;
    const int lt   = tid & 127;
    const int vh   = lt & 1;
    const int d0   = (lt >> 1) * 4;
    const int v0   = vh * 16;
    const int pbase = blockIdx.x * 512 + half * 256;

    ull acc[4][8];   // acc[dd][j] <-> d=d0+dd, v=v0+2j..+2
    #pragma unroll
    for(int a=0;a<4;a++)
        #pragma unroll
        for(int b=0;b<8;b++) acc[a][b]=0;
    float svec[8];
    #pragma unroll
    for(int i=0;i<8;i++) svec[i]=0.0f;

    const float4* qsrc = (const float4*)(g_Q + (size_t)pbase*VV);
    float4 qn0 = qsrc[lt*2], qn1 = qsrc[lt*2+1];

    for(int it=0; it<8; it++){
        __syncthreads();
        ((float4*)qs[half])[lt*2]   = qn0;
        ((float4*)qs[half])[lt*2+1] = qn1;
        svec[0]+=qn0.x; svec[1]+=qn0.y; svec[2]+=qn0.z; svec[3]+=qn0.w;
        svec[4]+=qn1.x; svec[5]+=qn1.y; svec[6]+=qn1.z; svec[7]+=qn1.w;
        __syncthreads();
        if(it+1 < 8){
            const float4* qn = (const float4*)(g_Q + (size_t)(pbase + (it+1)*32)*VV);
            qn0 = qn[lt*2]; qn1 = qn[lt*2+1];
        }

        const float* xp = X + (size_t)(pbase + it*32)*DD + d0;
        #pragma unroll
        for(int pb=0; pb<32; pb+=8){
            float4 x[8];
            #pragma unroll
            for(int k=0;k<8;k++) x[k] = *(const float4*)(xp + (pb+k)*DD);  // coalesced
            #pragma unroll
            for(int k=0;k<8;k++){
                const ulonglong2* qrow = (const ulonglong2*)(qs[half] + (pb+k)*VV + v0);
                ulonglong2 qa = qrow[0], qb = qrow[1], qc = qrow[2], qd = qrow[3];
                float xs4[4] = {x[k].x, x[k].y, x[k].z, x[k].w};
                #pragma unroll
                for(int dd=0; dd<4; dd++){
                    ull xv = pk2(xs4[dd], xs4[dd]);
                    acc[dd][0] = f2fma(xv, qa.x, acc[dd][0]);
                    acc[dd][1] = f2fma(xv, qa.y, acc[dd][1]);
                    acc[dd][2] = f2fma(xv, qb.x, acc[dd][2]);
                    acc[dd][3] = f2fma(xv, qb.y, acc[dd][3]);
                    acc[dd][4] = f2fma(xv, qc.x, acc[dd][4]);
                    acc[dd][5] = f2fma(xv, qc.y, acc[dd][5]);
                    acc[dd][6] = f2fma(xv, qd.x, acc[dd][6]);
                    acc[dd][7] = f2fma(xv, qd.y, acc[dd][7]);
                }
            }
        }
    }
    // store partials: thread covers d=d0..+4, v=v0..+16
    float* mp = g_Mpart + (size_t)(blockIdx.x*2 + half)*DD*VV;
    #pragma unroll
    for(int dd=0; dd<4; dd++){
        float* row = mp + (d0+dd)*VV + v0;
        #pragma unroll
        for(int j=0;j<8;j++){
            float2 f = up2(acc[dd][j]);
            row[2*j] = f.x; row[2*j+1] = f.y;
        }
    }
    // colsum partials (staging mapping identical to v4)
    #pragma unroll
    for(int i=0;i<8;i++) ssh[tid*8+i] = svec[i];
    __syncthreads();
    if(tid < 2*VV){
        int h = tid >> 5, v = tid & 31;
        float s = 0.0f;
        #pragma unroll
        for(int g=0; g<32; g++) s += ssh[(h*128 + g*4 + (v>>3))*8 + (v&7)];
        g_spart[(blockIdx.x*2 + h)*VV + v] = s;
    }
}

// ---------------- kernel 2a: two-stage deterministic reduction ------------
__global__ void k_reduceA(){
    int pg = blockIdx.x >> 5;
    int ec = blockIdx.x & 31;
    int e  = ec*256 + threadIdx.x;
    const float* base = g_Mpart + (size_t)pg*64*DD*VV + e;
    float s0=0.f, s1=0.f, s2=0.f, s3=0.f;
    for(int p=0; p<64; p+=4){
        s0 += base[(size_t)(p  )*DD*VV];
        s1 += base[(size_t)(p+1)*DD*VV];
        s2 += base[(size_t)(p+2)*DD*VV];
        s3 += base[(size_t)(p+3)*DD*VV];
    }
    g_M2[pg*DD*VV + e] = (s0+s1)+(s2+s3);
}
__global__ void k_reduceB(){
    if(blockIdx.x < 32){
        int e = blockIdx.x*256 + threadIdx.x;
        float s = 0.0f;
        #pragma unroll
        for(int g=0; g<16; g++) s += g_M2[g*DD*VV + e];
        g_M[e] = s;
    } else {
        __shared__ float sh[256];
        int v = threadIdx.x & 31, grp = threadIdx.x >> 5;
        float s = 0.0f;
        for(int p=grp; p<NPARTS2; p+=8) s += g_spart[p*VV + v];
        sh[threadIdx.x] = s;
        __syncthreads();
        if(threadIdx.x < VV){
            float t = 0.0f;
            #pragma unroll
            for(int g=0; g<8; g++) t += sh[g*32 + threadIdx.x];
            g_s[threadIdx.x] = t;
        }
    }
}

// ---------------- kernel 2b: Z, normalize, Adj = Z^T Z --------------------
__global__ __launch_bounds__(256) void k_z(const float* __restrict__ W,
                                           const float* __restrict__ var){
    __shared__ float Zs[DD*33];
    __shared__ float s_s[VV], cs[VV];
    const int tid = threadIdx.x;
    if(tid < VV) s_s[tid] = g_s[tid];
    __syncthreads();

    #pragma unroll
    for(int v=0; v<VV; v++){
        int e = tid*VV + v;
        float sv = s_s[v];
        float z = (g_M[e] - W[e]*sv) * (1.0f/var[e]) / sv;
        Zs[tid*33 + v] = z;
    }
    __syncthreads();
    if(tid < VV){
        float acc = 0.0f;
        for(int d=0; d<DD; d++){ float z = Zs[d*33+tid]; acc = fmaf(z,z,acc); }
        cs[tid] = acc;
    }
    __syncthreads();
    #pragma unroll
    for(int v=0; v<VV; v++){
        float z = Zs[tid*33 + v] / cs[v];
        Zs[tid*33 + v] = z;
        g_Z[tid*VV + v] = z;
    }
    __syncthreads();
    for(int k=0;k<4;k++){
        int e = k*256 + tid;
        int i = e >> 5, j = e & 31;
        float acc = 0.0f;
        for(int d=0; d<DD; d++) acc = fmaf(Zs[d*33+i], Zs[d*33+j], acc);
        g_Adj[e] = acc;
    }
}

// ---------------- kernel 2c/2d: T1, Zo ------------------------------------
__global__ void k_t1(const float* __restrict__ weight){
    int v = blockIdx.x, f = threadIdx.x;
    float acc = 0.0f;
    for(int d=0; d<DD; d++) acc = fmaf(g_Z[d*VV+v], weight[d*NF+f], acc);
    g_T1[v*NF + f] = acc;
}
__global__ void k_zo(){
    int v = blockIdx.x, f = threadIdx.x;
    float acc = 0.0f;
    #pragma unroll
    for(int j=0;j<VV;j++) acc = fmaf(g_Adj[v*VV+j], g_T1[j*NF+f], acc);
    g_Zo[v*NF + f] = fmaxf(acc, 0.0f);
}

// ---------------- kernel 3: Xn = Q @ Zo -> out ----------------------------
__global__ __launch_bounds__(256) void k_out(float* __restrict__ out){
    __shared__ __align__(16) float zo[VV*NF];
    __shared__ __align__(16) float qts[8][264];

    const int tid = threadIdx.x, w = tid >> 5, l = tid & 31;
    for(int i=tid; i<VV*NF; i+=256) zo[i] = g_Zo[i];
    __syncthreads();

    const int pbase = blockIdx.x*64 + w*8;
    {
        const float4* src = (const float4*)(g_Q + (size_t)(pbase + (l>>2))*VV + (l&3)*8);
        float4 a = src[0], b = src[1];
        int p = l >> 2, vb = (l & 3)*8;
        float* dst = qts[w];
        dst[(vb+0)*8+p]=a.x; dst[(vb+1)*8+p]=a.y; dst[(vb+2)*8+p]=a.z; dst[(vb+3)*8+p]=a.w;
        dst[(vb+4)*8+p]=b.x; dst[(vb+5)*8+p]=b.y; dst[(vb+6)*8+p]=b.z; dst[(vb+7)*8+p]=b.w;
    }
    __syncwarp();

    ull acc[8][4];
    #pragma unroll
    for(int p=0;p<8;p++){ acc[p][0]=0; acc[p][1]=0; acc[p][2]=0; acc[p][3]=0; }

    #pragma unroll 4
    for(int v=0; v<VV; v++){
        ulonglong2 zA = *(const ulonglong2*)(zo + v*NF + l*4);
        ulonglong2 zB = *(const ulonglong2*)(zo + v*NF + 128 + l*4);
        const float* qv = qts[w] + v*8;
        float4 qA = *(const float4*)(qv);
        float4 qB = *(const float4*)(qv+4);
        float qf[8] = {qA.x,qA.y,qA.z,qA.w,qB.x,qB.y,qB.z,qB.w};
        #pragma unroll
        for(int p=0;p<8;p++){
            ull qp = pk2(qf[p], qf[p]);
            acc[p][0] = f2fma(qp, zA.x, acc[p][0]);
            acc[p][1] = f2fma(qp, zA.y, acc[p][1]);
            acc[p][2] = f2fma(qp, zB.x, acc[p][2]);
            acc[p][3] = f2fma(qp, zB.y, acc[p][3]);
        }
    }
    #pragma unroll
    for(int p=0;p<8;p++){
        float2 f0=up2(acc[p][0]), f1=up2(acc[p][1]);
        float2 f2v=up2(acc[p][2]), f3=up2(acc[p][3]);
        float* base = out + (size_t)(pbase+p)*NF;
        *(float4*)(base + l*4)       = make_float4(f0.x,f0.y,f1.x,f1.y);
        *(float4*)(base + 128 + l*4) = make_float4(f2v.x,f2v.y,f3.x,f3.y);
    }
}

// ---------------- launch ---------------------------------------------------
extern "C" void kernel_launch(void* const* d_in, const int* in_sizes, int n_in,
                              void* d_out, int out_size){
    const float* X      = (const float*)d_in[0];
    const float* W      = (const float*)d_in[1];
    const float* var    = (const float*)d_in[2];
    const float* weight = (const float*)d_in[3];
    float* out = (float*)d_out;

    static int smem_set = 0;
    const int qp_smem = (DD*VV*2 + 32) * 4;
    if(!smem_set){
        cudaFuncSetAttribute(k_qpass, cudaFuncAttributeMaxDynamicSharedMemorySize, qp_smem);
        smem_set = 1;
    }

    k_prep   <<<32, 256>>>(W, var);
    k_prep_c <<<1, 32>>>(W);
    k_qpass  <<<HW/512, 256, qp_smem>>>(X);
    k_mpass  <<<NPART, 256>>>(X);
    k_reduceA<<<512, 256>>>();
    k_reduceB<<<33, 256>>>();
    k_z      <<<1, 256>>>(W, var);
    k_t1     <<<VV, 256>>>(weight);
    k_zo     <<<VV, 256>>>();
    k_out    <<<HW/64, 256>>>(out);
}